// round 14
// baseline (speedup 1.0000x reference)
#include <cuda_runtime.h>
#include <cstdint>
#include <math.h>

#define D    128
#define S_MAX 125000
#define EPS  1e-13f

__device__ int g_starts[S_MAX + 1];      // segment start offsets

// ---------------------------------------------------------------------------
// Kernel 1: segment start offsets from the sorted index array (int4 scan).
// ---------------------------------------------------------------------------
__global__ void seg_starts_kernel(const int* __restrict__ idx, int N, int S) {
    int t  = blockIdx.x * blockDim.x + threadIdx.x;
    int n0 = t * 4;
    if (n0 >= N) return;

    int v0, v1, v2, v3;
    if (n0 + 3 < N) {
        int4 c = *(const int4*)(idx + n0);
        v0 = c.x; v1 = c.y; v2 = c.z; v3 = c.w;
    } else {
        v0 = idx[n0];
        v1 = (n0 + 1 < N) ? idx[n0 + 1] : v0;
        v2 = (n0 + 2 < N) ? idx[n0 + 2] : v1;
        v3 = (n0 + 3 < N) ? idx[n0 + 3] : v2;
    }
    int prev = (n0 == 0) ? -1 : idx[n0 - 1];

    int vals[4] = {v0, v1, v2, v3};
    #pragma unroll
    for (int j = 0; j < 4; ++j) {
        if (n0 + j < N) {
            int cur = vals[j];
            for (int s = prev + 1; s <= cur; ++s) g_starts[s] = n0 + j;
            prev = cur;
        }
    }
    if (n0 + 4 >= N) {
        for (int s = prev + 1; s <= S; ++s) g_starts[s] = N;
    }
}

__device__ __forceinline__ float dot4(float4 a, float4 b) {
    return a.x * b.x + a.y * b.y + a.z * b.z + a.w * b.w;
}

__device__ __forceinline__ uint32_t f2tf32(float f) {
    uint32_t r;
    asm("cvt.rna.tf32.f32 %0, %1;" : "=r"(r) : "f"(f));
    return r;
}

__device__ __forceinline__ void mma_tf32(float* c, const uint32_t* a, const uint32_t* b) {
    asm volatile(
        "mma.sync.aligned.m16n8k8.row.col.f32.tf32.tf32.f32 "
        "{%0,%1,%2,%3}, {%4,%5,%6,%7}, {%8,%9}, {%0,%1,%2,%3};\n"
        : "+f"(c[0]), "+f"(c[1]), "+f"(c[2]), "+f"(c[3])
        : "r"(a[0]), "r"(a[1]), "r"(a[2]), "r"(a[3]), "r"(b[0]), "r"(b[1]));
}

// ---------------------------------------------------------------------------
// FUSED kernel, BM=64 (exact R12 structure = record holder) + L2 PREFETCH.
// Phase 1: 8 warps x 8 consecutive segments. Per 4-row batch, each lane
// issues prefetch.global.L2 for one 128B line 16 rows ahead (32 lanes cover
// 8 rows). Costs no data registers; converts later LDGs from DRAM latency
// (~577cyc) to L2 latency (~250cyc) -- the direct fix for the measured
// latency-bound phase 1 (regs/warps are both maxed out).
// ---------------------------------------------------------------------------
#define BM 64
#define BN 128
#define BK 32
#define YSTR 36
#define WSTR (BN + 4)
// dynamic smem floats: Y 4*64*36 = 9216 | wS 32*132 = 4224 | sg 64
#define SM_Y   0
#define SM_W   9216
#define SM_SG  (9216 + 4224)
#define SMEM_FLOATS (9216 + 4224 + 64)

__global__ void __launch_bounds__(256, 4)
fused_kernel(const float* __restrict__ x,
             const float* __restrict__ w,
             const float* __restrict__ Wg,
             const float* __restrict__ bgp,
             const float* __restrict__ Wm,
             const float* __restrict__ bm,
             float* __restrict__ out, int S, int Nrows) {
    extern __shared__ float sm[];
    float* Y  = sm + SM_Y;    // [4][64][36]
    float* wS = sm + SM_W;    // [32][132]
    float* SG = sm + SM_SG;   // [64]

    int tid  = threadIdx.x;
    int wid  = tid >> 5;
    int lane = tid & 31;
    int segbase = blockIdx.x * BM;

    // ===================== Phase 1: aggregation into SMEM =====================
    {
        int q   = lane >> 3;
        int pm1 = q ^ 1, pm2 = q ^ 2, pm3 = q ^ 3;
        float4 wg  = *(const float4*)(Wg + lane * 4);
        float  bg0 = bgp[0];

        int chunk = lane >> 3;            // K-chunk this lane's columns live in
        int ccol  = (lane & 7) * 4;       // column within chunk

        int s_first = segbase + wid * 8;
        int sf = s_first; if (sf > S) sf = S;
        int r0 = g_starts[sf];

        for (int i = 0; i < 8; ++i) {
            int s     = s_first + i;
            int local = wid * 8 + i;
            int r1  = (s < S) ? g_starts[s + 1] : r0;
            int len = r1 - r0;
            const float* xb = x + (size_t)r0 * D + lane * 4;

            float4 acc = make_float4(0.f, 0.f, 0.f, 0.f);
            float  denom = 0.f;

            for (int base = 0; base < len; base += 4) {
                // L2 prefetch: 32 lanes cover rows [r0+base+16, r0+base+24)
                {
                    int pr = r0 + base + 16;
                    if (pr + 8 <= Nrows) {
                        const float* pf = x + (size_t)pr * D + lane * 32;
                        asm volatile("prefetch.global.L2 [%0];" :: "l"(pf));
                    }
                }

                int rA = base + q;
                int rB = base + pm1;
                int rC = base + pm2;
                int rD = base + pm3;

                float4 v0 = make_float4(0.f,0.f,0.f,0.f), v1 = v0, v2 = v0, v3 = v0;
                if (rA < len) v0 = *(const float4*)(xb + (size_t)rA * D);
                if (rB < len) v1 = *(const float4*)(xb + (size_t)rB * D);
                if (rC < len) v2 = *(const float4*)(xb + (size_t)rC * D);
                if (rD < len) v3 = *(const float4*)(xb + (size_t)rD * D);
                float wr = (rA < len) ? w[r0 + rA] : 0.f;

                float p0 = dot4(v0, wg);
                float p1 = dot4(v1, wg);
                float p2 = dot4(v2, wg);
                float p3 = dot4(v3, wg);

                float t01 = p0 + __shfl_xor_sync(0xffffffffu, p1, 8);
                float t23 = p2 + __shfl_xor_sync(0xffffffffu, p3, 8);
                float t   = t01 + __shfl_xor_sync(0xffffffffu, t23, 16);
                t += __shfl_xor_sync(0xffffffffu, t, 1);
                t += __shfl_xor_sync(0xffffffffu, t, 2);
                t += __shfl_xor_sync(0xffffffffu, t, 4);

                float g = wr * __expf(t + bg0);
                denom += g;

                float g1 = __shfl_xor_sync(0xffffffffu, g, 8);
                float g2 = __shfl_xor_sync(0xffffffffu, g, 16);
                float g3 = __shfl_xor_sync(0xffffffffu, g, 24);

                acc.x += g * v0.x + g1 * v1.x + g2 * v2.x + g3 * v3.x;
                acc.y += g * v0.y + g1 * v1.y + g2 * v2.y + g3 * v3.y;
                acc.z += g * v0.z + g1 * v1.z + g2 * v2.z + g3 * v3.z;
                acc.w += g * v0.w + g1 * v1.w + g2 * v2.w + g3 * v3.w;
            }

            denom += __shfl_xor_sync(0xffffffffu, denom, 8);
            denom += __shfl_xor_sync(0xffffffffu, denom, 16);

            float inv = 1.f / (denom + EPS);
            float4 o;
            o.x = acc.x * inv; o.y = acc.y * inv;
            o.z = acc.z * inv; o.w = acc.w * inv;
            *(float4*)(Y + chunk * (BM * YSTR) + local * YSTR + ccol) = o;
            if (lane == 0) SG[local] = denom * inv;

            r0 = r1;
        }
    }

    // ===================== Phase 2: tf32 MMA gemm from SMEM =====================
    int warp_m = wid & 1;     // 2 warps along M (32 rows each)
    int warp_n = wid >> 1;    // 4 warps along N (32 cols each)
    int grp = lane >> 2;
    int tg  = lane & 3;

    float c[2][4][4];
    #pragma unroll
    for (int mf = 0; mf < 2; ++mf)
        #pragma unroll
        for (int nf = 0; nf < 4; ++nf)
            #pragma unroll
            for (int i = 0; i < 4; ++i) c[mf][nf][i] = 0.f;

    for (int kt = 0; kt < D; kt += BK) {
        __syncthreads();   // at kt=0 this is also the phase-1/phase-2 boundary
        {
            int k = tid >> 3;
            #pragma unroll
            for (int it = 0; it < 4; ++it) {
                int q2 = (tid & 7) + it * 8;
                *(float4*)(wS + k * WSTR + q2 * 4) =
                    *(const float4*)(Wm + (size_t)(kt + k) * D + q2 * 4);
            }
        }
        __syncthreads();

        const float* Yc = Y + (kt >> 5) * (BM * YSTR);

        #pragma unroll
        for (int ks = 0; ks < BK; ks += 8) {
            uint32_t a[2][4];
            uint32_t b[4][2];
            #pragma unroll
            for (int mf = 0; mf < 2; ++mf) {
                int r = warp_m * 32 + mf * 16;
                a[mf][0] = f2tf32(Yc[(r + grp    ) * YSTR + ks + tg    ]);
                a[mf][1] = f2tf32(Yc[(r + grp + 8) * YSTR + ks + tg    ]);
                a[mf][2] = f2tf32(Yc[(r + grp    ) * YSTR + ks + tg + 4]);
                a[mf][3] = f2tf32(Yc[(r + grp + 8) * YSTR + ks + tg + 4]);
            }
            #pragma unroll
            for (int nf = 0; nf < 4; ++nf) {
                int col = warp_n * 32 + nf * 8 + grp;
                b[nf][0] = f2tf32(wS[(ks + tg    ) * WSTR + col]);
                b[nf][1] = f2tf32(wS[(ks + tg + 4) * WSTR + col]);
            }
            #pragma unroll
            for (int mf = 0; mf < 2; ++mf)
                #pragma unroll
                for (int nf = 0; nf < 4; ++nf)
                    mma_tf32(c[mf][nf], a[mf], b[nf]);
        }
    }

    // Epilogue: out = c + sg[row] * bm[col]
    #pragma unroll
    for (int mf = 0; mf < 2; ++mf) {
        int lrow0 = warp_m * 32 + mf * 16 + grp;
        int lrow1 = lrow0 + 8;
        int row0 = segbase + lrow0;
        int row1 = segbase + lrow1;
        float sgA = SG[lrow0];
        float sgB = SG[lrow1];
        #pragma unroll
        for (int nf = 0; nf < 4; ++nf) {
            int col = warp_n * 32 + nf * 8 + tg * 2;
            float b0 = bm[col], b1 = bm[col + 1];
            if (row0 < S) {
                float2 o;
                o.x = c[mf][nf][0] + sgA * b0;
                o.y = c[mf][nf][1] + sgA * b1;
                *(float2*)(out + (size_t)row0 * D + col) = o;
            }
            if (row1 < S) {
                float2 o;
                o.x = c[mf][nf][2] + sgB * b0;
                o.y = c[mf][nf][3] + sgB * b1;
                *(float2*)(out + (size_t)row1 * D + col) = o;
            }
        }
    }
}

// ---------------------------------------------------------------------------
extern "C" void kernel_launch(void* const* d_in, const int* in_sizes, int n_in,
                              void* d_out, int out_size) {
    const float* x   = (const float*)d_in[0];
    const int*   idx = (const int*)  d_in[1];
    const float* w   = (const float*)d_in[2];
    const float* Wg  = (const float*)d_in[3];
    const float* bg  = (const float*)d_in[4];
    const float* Wm  = (const float*)d_in[5];
    const float* bm  = (const float*)d_in[6];
    float* out = (float*)d_out;

    int N = in_sizes[1];
    int S = out_size / D;

    int quads = (N + 3) / 4;
    seg_starts_kernel<<<(quads + 255) / 256, 256>>>(idx, N, S);

    static int smem_set = 0;
    if (!smem_set) {
        cudaFuncSetAttribute(fused_kernel,
                             cudaFuncAttributeMaxDynamicSharedMemorySize,
                             SMEM_FLOATS * 4);
        smem_set = 1;
    }
    int blocks = (S + BM - 1) / BM;
    fused_kernel<<<blocks, 256, SMEM_FLOATS * 4>>>(x, w, Wg, bg, Wm, bm, out, S, N);
}

// round 15
// speedup vs baseline: 1.4541x; 1.4541x over previous
#include <cuda_runtime.h>
#include <cstdint>
#include <math.h>

#define D    128
#define S_MAX 125000
#define EPS  1e-13f

__device__ int g_starts[S_MAX + 1];      // segment start offsets

// ---------------------------------------------------------------------------
// Kernel 1: segment start offsets from the sorted index array (int4 scan).
// ---------------------------------------------------------------------------
__global__ void seg_starts_kernel(const int* __restrict__ idx, int N, int S) {
    int t  = blockIdx.x * blockDim.x + threadIdx.x;
    int n0 = t * 4;
    if (n0 >= N) return;

    int v0, v1, v2, v3;
    if (n0 + 3 < N) {
        int4 c = *(const int4*)(idx + n0);
        v0 = c.x; v1 = c.y; v2 = c.z; v3 = c.w;
    } else {
        v0 = idx[n0];
        v1 = (n0 + 1 < N) ? idx[n0 + 1] : v0;
        v2 = (n0 + 2 < N) ? idx[n0 + 2] : v1;
        v3 = (n0 + 3 < N) ? idx[n0 + 3] : v2;
    }
    int prev = (n0 == 0) ? -1 : idx[n0 - 1];

    int vals[4] = {v0, v1, v2, v3};
    #pragma unroll
    for (int j = 0; j < 4; ++j) {
        if (n0 + j < N) {
            int cur = vals[j];
            for (int s = prev + 1; s <= cur; ++s) g_starts[s] = n0 + j;
            prev = cur;
        }
    }
    if (n0 + 4 >= N) {
        for (int s = prev + 1; s <= S; ++s) g_starts[s] = N;
    }
}

__device__ __forceinline__ float dot4(float4 a, float4 b) {
    return a.x * b.x + a.y * b.y + a.z * b.z + a.w * b.w;
}

__device__ __forceinline__ uint32_t f2tf32(float f) {
    uint32_t r;
    asm("cvt.rna.tf32.f32 %0, %1;" : "=r"(r) : "f"(f));
    return r;
}

__device__ __forceinline__ void mma_tf32(float* c, const uint32_t* a, const uint32_t* b) {
    asm volatile(
        "mma.sync.aligned.m16n8k8.row.col.f32.tf32.tf32.f32 "
        "{%0,%1,%2,%3}, {%4,%5,%6,%7}, {%8,%9}, {%0,%1,%2,%3};\n"
        : "+f"(c[0]), "+f"(c[1]), "+f"(c[2]), "+f"(c[3])
        : "r"(a[0]), "r"(a[1]), "r"(a[2]), "r"(a[3]), "r"(b[0]), "r"(b[1]));
}

__device__ __forceinline__ void cp_async16(uint32_t dst, const float* src) {
    asm volatile("cp.async.cg.shared.global [%0], [%1], 16;" :: "r"(dst), "l"(src));
}
#define CP_COMMIT() asm volatile("cp.async.commit_group;")
#define CP_WAIT(n)  asm volatile("cp.async.wait_group %0;" :: "n"(n))

// ---------------------------------------------------------------------------
// FUSED kernel, BM=64 (R12 structure) + cp.async row ring for phase 1.
// Each warp streams its contiguous row range [rs,re) through an 8-slot smem
// ring (row = 512B; lane l copies/reads only bytes [16l,16l+16) -> per-thread
// cp.async.wait_group is sufficient, no barriers in the loop). Before batch
// [b,b+4): issue rows < min(b+8,re), wait_group(4) (or 0 when clamped).
// Data registers freed -> 8 rows in flight/warp; 3 blocks/SM (70KB smem).
// Ring region aliases wS (phase-2 only); CP_WAIT(0) guards the boundary.
// ---------------------------------------------------------------------------
#define BM 64
#define BN 128
#define BK 32
#define YSTR 36
#define WSTR (BN + 4)
// dynamic smem floats: Y 4*64*36 = 9216 | ring 8w*8slots*128 = 8192 (aliases wS) | sg 64
#define SM_Y    0
#define SM_RING 9216
#define SM_SG   (9216 + 8192)
#define SMEM_FLOATS (9216 + 8192 + 64)

__global__ void __launch_bounds__(256, 3)
fused_kernel(const float* __restrict__ x,
             const float* __restrict__ w,
             const float* __restrict__ Wg,
             const float* __restrict__ bgp,
             const float* __restrict__ Wm,
             const float* __restrict__ bm,
             float* __restrict__ out, int S) {
    extern __shared__ float sm[];
    float* Y  = sm + SM_Y;       // [4][64][36]
    float* wS = sm + SM_RING;    // [32][132]  (phase 2 only; aliases ring)
    float* SG = sm + SM_SG;      // [64]

    int tid  = threadIdx.x;
    int wid  = tid >> 5;
    int lane = tid & 31;
    int segbase = blockIdx.x * BM;

    // ===================== Phase 1: aggregation into SMEM =====================
    {
        int q   = lane >> 3;
        int pm1 = q ^ 1, pm2 = q ^ 2, pm3 = q ^ 3;
        float4 wg  = *(const float4*)(Wg + lane * 4);
        float  bg0 = bgp[0];

        int chunk = lane >> 3;            // K-chunk this lane's columns live in
        int ccol  = (lane & 7) * 4;       // column within chunk

        // per-warp ring
        const float* ringw = sm + SM_RING + wid * 1024;           // reads
        uint32_t ring_u32 = (uint32_t)__cvta_generic_to_shared(sm + SM_RING)
                          + wid * 4096 + (lane << 4);             // writes (bytes)

        int s_first = segbase + wid * 8;
        int sf = s_first; if (sf > S) sf = S;
        int se = s_first + 8; if (se > S) se = S; if (se < sf) se = sf;
        int rs = g_starts[sf];
        int re = g_starts[se];
        int ifetch = rs;

        int r0 = rs;
        for (int i = 0; i < 8; ++i) {
            int s     = s_first + i;
            int local = wid * 8 + i;
            int r1  = (s < S) ? g_starts[s + 1] : r0;
            int len = r1 - r0;

            float4 acc = make_float4(0.f, 0.f, 0.f, 0.f);
            float  denom = 0.f;

            for (int base = 0; base < len; base += 4) {
                int b = r0 + base;
                // issue rows [ifetch, min(b+8,re)) into the ring
                int tgt = b + 8; if (tgt > re) tgt = re;
                for (; ifetch < tgt; ++ifetch) {
                    cp_async16(ring_u32 + ((ifetch & 7) << 9),
                               x + ((size_t)ifetch << 7) + (lane << 2));
                    CP_COMMIT();
                }
                if (b + 8 > re) { CP_WAIT(0); } else { CP_WAIT(4); }

                int rA = base + q;
                int rB = base + pm1;
                int rC = base + pm2;
                int rD = base + pm3;

                float4 v0 = make_float4(0.f,0.f,0.f,0.f), v1 = v0, v2 = v0, v3 = v0;
                if (rA < len) v0 = *(const float4*)(ringw + (((r0 + rA) & 7) << 7) + (lane << 2));
                if (rB < len) v1 = *(const float4*)(ringw + (((r0 + rB) & 7) << 7) + (lane << 2));
                if (rC < len) v2 = *(const float4*)(ringw + (((r0 + rC) & 7) << 7) + (lane << 2));
                if (rD < len) v3 = *(const float4*)(ringw + (((r0 + rD) & 7) << 7) + (lane << 2));
                float wr = (rA < len) ? w[r0 + rA] : 0.f;

                float p0 = dot4(v0, wg);
                float p1 = dot4(v1, wg);
                float p2 = dot4(v2, wg);
                float p3 = dot4(v3, wg);

                float t01 = p0 + __shfl_xor_sync(0xffffffffu, p1, 8);
                float t23 = p2 + __shfl_xor_sync(0xffffffffu, p3, 8);
                float t   = t01 + __shfl_xor_sync(0xffffffffu, t23, 16);
                t += __shfl_xor_sync(0xffffffffu, t, 1);
                t += __shfl_xor_sync(0xffffffffu, t, 2);
                t += __shfl_xor_sync(0xffffffffu, t, 4);

                float g = wr * __expf(t + bg0);
                denom += g;

                float g1 = __shfl_xor_sync(0xffffffffu, g, 8);
                float g2 = __shfl_xor_sync(0xffffffffu, g, 16);
                float g3 = __shfl_xor_sync(0xffffffffu, g, 24);

                acc.x += g * v0.x + g1 * v1.x + g2 * v2.x + g3 * v3.x;
                acc.y += g * v0.y + g1 * v1.y + g2 * v2.y + g3 * v3.y;
                acc.z += g * v0.z + g1 * v1.z + g2 * v2.z + g3 * v3.z;
                acc.w += g * v0.w + g1 * v1.w + g2 * v2.w + g3 * v3.w;
            }

            denom += __shfl_xor_sync(0xffffffffu, denom, 8);
            denom += __shfl_xor_sync(0xffffffffu, denom, 16);

            float inv = 1.f / (denom + EPS);
            float4 o;
            o.x = acc.x * inv; o.y = acc.y * inv;
            o.z = acc.z * inv; o.w = acc.w * inv;
            *(float4*)(Y + chunk * (BM * YSTR) + local * YSTR + ccol) = o;
            if (lane == 0) SG[local] = denom * inv;

            r0 = r1;
        }

        CP_WAIT(0);   // drain pending cp.async before ring is reused as wS
    }

    // ===================== Phase 2: tf32 MMA gemm from SMEM =====================
    int warp_m = wid & 1;     // 2 warps along M (32 rows each)
    int warp_n = wid >> 1;    // 4 warps along N (32 cols each)
    int grp = lane >> 2;
    int tg  = lane & 3;

    float c[2][4][4];
    #pragma unroll
    for (int mf = 0; mf < 2; ++mf)
        #pragma unroll
        for (int nf = 0; nf < 4; ++nf)
            #pragma unroll
            for (int i = 0; i < 4; ++i) c[mf][nf][i] = 0.f;

    for (int kt = 0; kt < D; kt += BK) {
        __syncthreads();   // at kt=0 this is also the phase-1/phase-2 boundary
        {
            int k = tid >> 3;
            #pragma unroll
            for (int it = 0; it < 4; ++it) {
                int q2 = (tid & 7) + it * 8;
                *(float4*)(wS + k * WSTR + q2 * 4) =
                    *(const float4*)(Wm + (size_t)(kt + k) * D + q2 * 4);
            }
        }
        __syncthreads();

        const float* Yc = Y + (kt >> 5) * (BM * YSTR);

        #pragma unroll
        for (int ks = 0; ks < BK; ks += 8) {
            uint32_t a[2][4];
            uint32_t b[4][2];
            #pragma unroll
            for (int mf = 0; mf < 2; ++mf) {
                int r = warp_m * 32 + mf * 16;
                a[mf][0] = f2tf32(Yc[(r + grp    ) * YSTR + ks + tg    ]);
                a[mf][1] = f2tf32(Yc[(r + grp + 8) * YSTR + ks + tg    ]);
                a[mf][2] = f2tf32(Yc[(r + grp    ) * YSTR + ks + tg + 4]);
                a[mf][3] = f2tf32(Yc[(r + grp + 8) * YSTR + ks + tg + 4]);
            }
            #pragma unroll
            for (int nf = 0; nf < 4; ++nf) {
                int col = warp_n * 32 + nf * 8 + grp;
                b[nf][0] = f2tf32(wS[(ks + tg    ) * WSTR + col]);
                b[nf][1] = f2tf32(wS[(ks + tg + 4) * WSTR + col]);
            }
            #pragma unroll
            for (int mf = 0; mf < 2; ++mf)
                #pragma unroll
                for (int nf = 0; nf < 4; ++nf)
                    mma_tf32(c[mf][nf], a[mf], b[nf]);
        }
    }

    // Epilogue: out = c + sg[row] * bm[col]
    #pragma unroll
    for (int mf = 0; mf < 2; ++mf) {
        int lrow0 = warp_m * 32 + mf * 16 + grp;
        int lrow1 = lrow0 + 8;
        int row0 = segbase + lrow0;
        int row1 = segbase + lrow1;
        float sgA = SG[lrow0];
        float sgB = SG[lrow1];
        #pragma unroll
        for (int nf = 0; nf < 4; ++nf) {
            int col = warp_n * 32 + nf * 8 + tg * 2;
            float b0 = bm[col], b1 = bm[col + 1];
            if (row0 < S) {
                float2 o;
                o.x = c[mf][nf][0] + sgA * b0;
                o.y = c[mf][nf][1] + sgA * b1;
                *(float2*)(out + (size_t)row0 * D + col) = o;
            }
            if (row1 < S) {
                float2 o;
                o.x = c[mf][nf][2] + sgB * b0;
                o.y = c[mf][nf][3] + sgB * b1;
                *(float2*)(out + (size_t)row1 * D + col) = o;
            }
        }
    }
}

// ---------------------------------------------------------------------------
extern "C" void kernel_launch(void* const* d_in, const int* in_sizes, int n_in,
                              void* d_out, int out_size) {
    const float* x   = (const float*)d_in[0];
    const int*   idx = (const int*)  d_in[1];
    const float* w   = (const float*)d_in[2];
    const float* Wg  = (const float*)d_in[3];
    const float* bg  = (const float*)d_in[4];
    const float* Wm  = (const float*)d_in[5];
    const float* bm  = (const float*)d_in[6];
    float* out = (float*)d_out;

    int N = in_sizes[1];
    int S = out_size / D;

    int quads = (N + 3) / 4;
    seg_starts_kernel<<<(quads + 255) / 256, 256>>>(idx, N, S);

    static int smem_set = 0;
    if (!smem_set) {
        cudaFuncSetAttribute(fused_kernel,
                             cudaFuncAttributeMaxDynamicSharedMemorySize,
                             SMEM_FLOATS * 4);
        smem_set = 1;
    }
    int blocks = (S + BM - 1) / BM;
    fused_kernel<<<blocks, 256, SMEM_FLOATS * 4>>>(x, w, Wg, bg, Wm, bm, out, S);
}

// round 16
// speedup vs baseline: 1.5030x; 1.0337x over previous
#include <cuda_runtime.h>
#include <cstdint>
#include <math.h>

#define D    128
#define S_MAX 125000
#define EPS  1e-13f

__device__ int g_starts[S_MAX + 1];      // segment start offsets

// ---------------------------------------------------------------------------
// Kernel 1: segment start offsets from the sorted index array (int4 scan).
// ---------------------------------------------------------------------------
__global__ void seg_starts_kernel(const int* __restrict__ idx, int N, int S) {
    int t  = blockIdx.x * blockDim.x + threadIdx.x;
    int n0 = t * 4;
    if (n0 >= N) return;

    int v0, v1, v2, v3;
    if (n0 + 3 < N) {
        int4 c = *(const int4*)(idx + n0);
        v0 = c.x; v1 = c.y; v2 = c.z; v3 = c.w;
    } else {
        v0 = idx[n0];
        v1 = (n0 + 1 < N) ? idx[n0 + 1] : v0;
        v2 = (n0 + 2 < N) ? idx[n0 + 2] : v1;
        v3 = (n0 + 3 < N) ? idx[n0 + 3] : v2;
    }
    int prev = (n0 == 0) ? -1 : idx[n0 - 1];

    int vals[4] = {v0, v1, v2, v3};
    #pragma unroll
    for (int j = 0; j < 4; ++j) {
        if (n0 + j < N) {
            int cur = vals[j];
            for (int s = prev + 1; s <= cur; ++s) g_starts[s] = n0 + j;
            prev = cur;
        }
    }
    if (n0 + 4 >= N) {
        for (int s = prev + 1; s <= S; ++s) g_starts[s] = N;
    }
}

__device__ __forceinline__ float dot4(float4 a, float4 b) {
    return a.x * b.x + a.y * b.y + a.z * b.z + a.w * b.w;
}

__device__ __forceinline__ uint32_t f2tf32(float f) {
    uint32_t r;
    asm("cvt.rna.tf32.f32 %0, %1;" : "=r"(r) : "f"(f));
    return r;
}

__device__ __forceinline__ void mma_tf32(float* c, const uint32_t* a, const uint32_t* b) {
    asm volatile(
        "mma.sync.aligned.m16n8k8.row.col.f32.tf32.tf32.f32 "
        "{%0,%1,%2,%3}, {%4,%5,%6,%7}, {%8,%9}, {%0,%1,%2,%3};\n"
        : "+f"(c[0]), "+f"(c[1]), "+f"(c[2]), "+f"(c[3])
        : "r"(a[0]), "r"(a[1]), "r"(a[2]), "r"(a[3]), "r"(b[0]), "r"(b[1]));
}

__device__ __forceinline__ void cp_async16(uint32_t dst, const float* src) {
    asm volatile("cp.async.cg.shared.global [%0], [%1], 16;" :: "r"(dst), "l"(src));
}
#define CP_COMMIT() asm volatile("cp.async.commit_group;")
#define CP_WAIT(n)  asm volatile("cp.async.wait_group %0;" :: "n"(n))

// ---------------------------------------------------------------------------
// FUSED kernel, BM=64 + cp.async row ring (R15 phase 1, record holder) +
// phase-2 cleanup: Y stored as tf32 bits, Wm -> tf32 at staging, WSTR=136
// (bank = 8tg+grp -> conflict-free b-frags). Mainloop = pure LDS + MMA.
// ---------------------------------------------------------------------------
#define BM 64
#define BN 128
#define BK 32
#define YSTR 36
#define WSTR 136
// dynamic smem words: Y 4*64*36 = 9216 | ring 8w*8slots*128 = 8192 (aliases wS 32*136=4352) | sg 64
#define SM_Y    0
#define SM_RING 9216
#define SM_SG   (9216 + 8192)
#define SMEM_WORDS (9216 + 8192 + 64)

__global__ void __launch_bounds__(256, 3)
fused_kernel(const float* __restrict__ x,
             const float* __restrict__ w,
             const float* __restrict__ Wg,
             const float* __restrict__ bgp,
             const float* __restrict__ Wm,
             const float* __restrict__ bm,
             float* __restrict__ out, int S) {
    extern __shared__ float sm[];
    uint32_t* Y  = (uint32_t*)(sm + SM_Y);     // [4][64][36] tf32 bits
    uint32_t* wS = (uint32_t*)(sm + SM_RING);  // [32][136] tf32 bits (phase 2; aliases ring)
    float*    SG = sm + SM_SG;                 // [64]

    int tid  = threadIdx.x;
    int wid  = tid >> 5;
    int lane = tid & 31;
    int segbase = blockIdx.x * BM;

    // ===================== Phase 1: aggregation into SMEM =====================
    {
        int q   = lane >> 3;
        int pm1 = q ^ 1, pm2 = q ^ 2, pm3 = q ^ 3;
        float4 wg  = *(const float4*)(Wg + lane * 4);
        float  bg0 = bgp[0];

        int chunk = lane >> 3;            // K-chunk this lane's columns live in
        int ccol  = (lane & 7) * 4;       // column within chunk

        // per-warp ring
        const float* ringw = sm + SM_RING + wid * 1024;           // reads
        uint32_t ring_u32 = (uint32_t)__cvta_generic_to_shared(sm + SM_RING)
                          + wid * 4096 + (lane << 4);             // writes (bytes)

        int s_first = segbase + wid * 8;
        int sf = s_first; if (sf > S) sf = S;
        int se = s_first + 8; if (se > S) se = S; if (se < sf) se = sf;
        int rs = g_starts[sf];
        int re = g_starts[se];
        int ifetch = rs;

        int r0 = rs;
        for (int i = 0; i < 8; ++i) {
            int s     = s_first + i;
            int local = wid * 8 + i;
            int r1  = (s < S) ? g_starts[s + 1] : r0;
            int len = r1 - r0;

            float4 acc = make_float4(0.f, 0.f, 0.f, 0.f);
            float  denom = 0.f;

            for (int base = 0; base < len; base += 4) {
                int b = r0 + base;
                // issue rows [ifetch, min(b+8,re)) into the ring
                int tgt = b + 8; if (tgt > re) tgt = re;
                for (; ifetch < tgt; ++ifetch) {
                    cp_async16(ring_u32 + ((ifetch & 7) << 9),
                               x + ((size_t)ifetch << 7) + (lane << 2));
                    CP_COMMIT();
                }
                if (b + 8 > re) { CP_WAIT(0); } else { CP_WAIT(4); }

                int rA = base + q;
                int rB = base + pm1;
                int rC = base + pm2;
                int rD = base + pm3;

                float4 v0 = make_float4(0.f,0.f,0.f,0.f), v1 = v0, v2 = v0, v3 = v0;
                if (rA < len) v0 = *(const float4*)(ringw + (((r0 + rA) & 7) << 7) + (lane << 2));
                if (rB < len) v1 = *(const float4*)(ringw + (((r0 + rB) & 7) << 7) + (lane << 2));
                if (rC < len) v2 = *(const float4*)(ringw + (((r0 + rC) & 7) << 7) + (lane << 2));
                if (rD < len) v3 = *(const float4*)(ringw + (((r0 + rD) & 7) << 7) + (lane << 2));
                float wr = (rA < len) ? w[r0 + rA] : 0.f;

                float p0 = dot4(v0, wg);
                float p1 = dot4(v1, wg);
                float p2 = dot4(v2, wg);
                float p3 = dot4(v3, wg);

                float t01 = p0 + __shfl_xor_sync(0xffffffffu, p1, 8);
                float t23 = p2 + __shfl_xor_sync(0xffffffffu, p3, 8);
                float t   = t01 + __shfl_xor_sync(0xffffffffu, t23, 16);
                t += __shfl_xor_sync(0xffffffffu, t, 1);
                t += __shfl_xor_sync(0xffffffffu, t, 2);
                t += __shfl_xor_sync(0xffffffffu, t, 4);

                float g = wr * __expf(t + bg0);
                denom += g;

                float g1 = __shfl_xor_sync(0xffffffffu, g, 8);
                float g2 = __shfl_xor_sync(0xffffffffu, g, 16);
                float g3 = __shfl_xor_sync(0xffffffffu, g, 24);

                acc.x += g * v0.x + g1 * v1.x + g2 * v2.x + g3 * v3.x;
                acc.y += g * v0.y + g1 * v1.y + g2 * v2.y + g3 * v3.y;
                acc.z += g * v0.z + g1 * v1.z + g2 * v2.z + g3 * v3.z;
                acc.w += g * v0.w + g1 * v1.w + g2 * v2.w + g3 * v3.w;
            }

            denom += __shfl_xor_sync(0xffffffffu, denom, 8);
            denom += __shfl_xor_sync(0xffffffffu, denom, 16);

            float inv = 1.f / (denom + EPS);
            uint4 o;
            o.x = f2tf32(acc.x * inv); o.y = f2tf32(acc.y * inv);
            o.z = f2tf32(acc.z * inv); o.w = f2tf32(acc.w * inv);
            *(uint4*)(Y + chunk * (BM * YSTR) + local * YSTR + ccol) = o;
            if (lane == 0) SG[local] = denom * inv;

            r0 = r1;
        }

        CP_WAIT(0);   // drain pending cp.async before ring is reused as wS
    }

    // ===================== Phase 2: tf32 MMA gemm from SMEM =====================
    int warp_m = wid & 1;     // 2 warps along M (32 rows each)
    int warp_n = wid >> 1;    // 4 warps along N (32 cols each)
    int grp = lane >> 2;
    int tg  = lane & 3;

    float c[2][4][4];
    #pragma unroll
    for (int mf = 0; mf < 2; ++mf)
        #pragma unroll
        for (int nf = 0; nf < 4; ++nf)
            #pragma unroll
            for (int i = 0; i < 4; ++i) c[mf][nf][i] = 0.f;

    for (int kt = 0; kt < D; kt += BK) {
        __syncthreads();   // at kt=0 this is also the phase-1/phase-2 boundary
        {
            int k = tid >> 3;
            #pragma unroll
            for (int it = 0; it < 4; ++it) {
                int q2 = (tid & 7) + it * 8;
                float4 t = *(const float4*)(Wm + (size_t)(kt + k) * D + q2 * 4);
                uint4 u;
                u.x = f2tf32(t.x); u.y = f2tf32(t.y);
                u.z = f2tf32(t.z); u.w = f2tf32(t.w);
                *(uint4*)(wS + k * WSTR + q2 * 4) = u;
            }
        }
        __syncthreads();

        const uint32_t* Yc = Y + (kt >> 5) * (BM * YSTR);

        #pragma unroll
        for (int ks = 0; ks < BK; ks += 8) {
            uint32_t a[2][4];
            uint32_t b[4][2];
            #pragma unroll
            for (int mf = 0; mf < 2; ++mf) {
                int r = warp_m * 32 + mf * 16;
                a[mf][0] = Yc[(r + grp    ) * YSTR + ks + tg    ];
                a[mf][1] = Yc[(r + grp + 8) * YSTR + ks + tg    ];
                a[mf][2] = Yc[(r + grp    ) * YSTR + ks + tg + 4];
                a[mf][3] = Yc[(r + grp + 8) * YSTR + ks + tg + 4];
            }
            #pragma unroll
            for (int nf = 0; nf < 4; ++nf) {
                int col = warp_n * 32 + nf * 8 + grp;
                b[nf][0] = wS[(ks + tg    ) * WSTR + col];
                b[nf][1] = wS[(ks + tg + 4) * WSTR + col];
            }
            #pragma unroll
            for (int mf = 0; mf < 2; ++mf)
                #pragma unroll
                for (int nf = 0; nf < 4; ++nf)
                    mma_tf32(c[mf][nf], a[mf], b[nf]);
        }
    }

    // Epilogue: out = c + sg[row] * bm[col]
    #pragma unroll
    for (int mf = 0; mf < 2; ++mf) {
        int lrow0 = warp_m * 32 + mf * 16 + grp;
        int lrow1 = lrow0 + 8;
        int row0 = segbase + lrow0;
        int row1 = segbase + lrow1;
        float sgA = SG[lrow0];
        float sgB = SG[lrow1];
        #pragma unroll
        for (int nf = 0; nf < 4; ++nf) {
            int col = warp_n * 32 + nf * 8 + tg * 2;
            float b0 = bm[col], b1 = bm[col + 1];
            if (row0 < S) {
                float2 o;
                o.x = c[mf][nf][0] + sgA * b0;
                o.y = c[mf][nf][1] + sgA * b1;
                *(float2*)(out + (size_t)row0 * D + col) = o;
            }
            if (row1 < S) {
                float2 o;
                o.x = c[mf][nf][2] + sgB * b0;
                o.y = c[mf][nf][3] + sgB * b1;
                *(float2*)(out + (size_t)row1 * D + col) = o;
            }
        }
    }
}

// ---------------------------------------------------------------------------
extern "C" void kernel_launch(void* const* d_in, const int* in_sizes, int n_in,
                              void* d_out, int out_size) {
    const float* x   = (const float*)d_in[0];
    const int*   idx = (const int*)  d_in[1];
    const float* w   = (const float*)d_in[2];
    const float* Wg  = (const float*)d_in[3];
    const float* bg  = (const float*)d_in[4];
    const float* Wm  = (const float*)d_in[5];
    const float* bm  = (const float*)d_in[6];
    float* out = (float*)d_out;

    int N = in_sizes[1];
    int S = out_size / D;

    int quads = (N + 3) / 4;
    seg_starts_kernel<<<(quads + 255) / 256, 256>>>(idx, N, S);

    static int smem_set = 0;
    if (!smem_set) {
        cudaFuncSetAttribute(fused_kernel,
                             cudaFuncAttributeMaxDynamicSharedMemorySize,
                             SMEM_WORDS * 4);
        smem_set = 1;
    }
    int blocks = (S + BM - 1) / BM;
    fused_kernel<<<blocks, 256, SMEM_WORDS * 4>>>(x, w, Wg, bg, Wm, bm, out, S);
}